// round 3
// baseline (speedup 1.0000x reference)
#include <cuda_runtime.h>
#include <cstdint>
#include <cstddef>

// Problem dims (fixed by the reference)
#define BB 8
#define LL 2048
#define DM 1024
#define HD 120
#define HP 128            // H padded to 128 with exact zeros
#define M_TOTAL (BB*LL)   // 16384

// -------- device scratch (no allocations allowed) --------
__device__ float g_ctx[M_TOTAL * HP];     // 8 MB, cols >=120 are 0
__device__ float g_trans[M_TOTAL * HP];   // 8 MB, cols >=120 are 0
__device__ float g_norm[M_TOTAL];
__device__ float g_rowsum[M_TOTAL];
__device__ float g_dw[HP * HP];           // W@W^T padded with zeros

// ---------------------------------------------------------
// Kernel: zero the rowsum accumulator
// ---------------------------------------------------------
__global__ void k_zero() {
    int i = blockIdx.x * blockDim.x + threadIdx.x;
    if (i < M_TOTAL) g_rowsum[i] = 0.0f;
}

// ---------------------------------------------------------
// Kernel: DW = W @ W^T, padded to 128x128 with zeros
// grid 128 blocks (one per row), 128 threads
// ---------------------------------------------------------
__global__ void k_dw(const float* __restrict__ W) {
    __shared__ float sw[HP];
    int i = blockIdx.x;     // output row
    int t = threadIdx.x;    // output col
    sw[t] = (i < HD && t < HD) ? W[i * HD + t] : 0.0f;
    __syncthreads();
    float acc = 0.0f;
    if (i < HD && t < HD) {
        const float* wr = W + t * HD;
        #pragma unroll 8
        for (int k = 0; k < HD; k++) acc = fmaf(sw[k], wr[k], acc);
    }
    g_dw[i * HP + t] = acc;   // acc==0 on padded rows/cols
}

// ---------------------------------------------------------
// Kernel: ctx[16384,128] = Q[16384,1024] @ qw^T + bias (cols>=120 -> 0)
// 128x128 tile, 256 threads, 8x8 microtile, Kc=16
// ---------------------------------------------------------
__global__ __launch_bounds__(256) void k_ctx(const float* __restrict__ Q,
                                             const float* __restrict__ qw,
                                             const float* __restrict__ qb) {
    __shared__ float sA[16][132];
    __shared__ float sB[16][132];
    const int m0 = blockIdx.x * 128;
    const int tid = threadIdx.x;
    const int tx = tid & 15, ty = tid >> 4;
    float acc[8][8] = {};

    for (int kc = 0; kc < DM; kc += 16) {
        #pragma unroll
        for (int r = 0; r < 2; r++) {
            int t4 = tid + 256 * r;
            int m  = t4 >> 2;
            int k4 = (t4 & 3) * 4;
            float4 v = *(const float4*)(Q + (size_t)(m0 + m) * DM + kc + k4);
            sA[k4 + 0][m] = v.x; sA[k4 + 1][m] = v.y;
            sA[k4 + 2][m] = v.z; sA[k4 + 3][m] = v.w;
        }
        #pragma unroll
        for (int r = 0; r < 2; r++) {
            int t4 = tid + 256 * r;
            int n  = t4 >> 2;
            int k4 = (t4 & 3) * 4;
            float4 v = make_float4(0.f, 0.f, 0.f, 0.f);
            if (n < HD) v = *(const float4*)(qw + (size_t)n * DM + kc + k4);
            sB[k4 + 0][n] = v.x; sB[k4 + 1][n] = v.y;
            sB[k4 + 2][n] = v.z; sB[k4 + 3][n] = v.w;
        }
        __syncthreads();
        #pragma unroll
        for (int k = 0; k < 16; k++) {
            float a[8], b[8];
            #pragma unroll
            for (int i = 0; i < 8; i++) a[i] = sA[k][ty * 8 + i];
            #pragma unroll
            for (int j = 0; j < 8; j++) b[j] = sB[k][tx * 8 + j];
            #pragma unroll
            for (int i = 0; i < 8; i++)
                #pragma unroll
                for (int j = 0; j < 8; j++)
                    acc[i][j] = fmaf(a[i], b[j], acc[i][j]);
        }
        __syncthreads();
    }
    #pragma unroll
    for (int i = 0; i < 8; i++) {
        int m = m0 + ty * 8 + i;
        #pragma unroll
        for (int j = 0; j < 8; j++) {
            int n = tx * 8 + j;
            float v = (n < HD) ? (acc[i][j] + qb[n]) : 0.0f;
            g_ctx[(size_t)m * HP + n] = v;
        }
    }
}

// ---------------------------------------------------------
// Kernel: trans = ctx @ DW (K=128), plus norm[m] = sum(trans*ctx)
// ---------------------------------------------------------
__global__ __launch_bounds__(256) void k_trans() {
    __shared__ float sA[16][132];
    __shared__ float sB[16][132];
    __shared__ float snorm[128];
    const int m0 = blockIdx.x * 128;
    const int tid = threadIdx.x;
    const int tx = tid & 15, ty = tid >> 4;
    float acc[8][8] = {};
    if (tid < 128) snorm[tid] = 0.0f;

    for (int kc = 0; kc < HP; kc += 16) {
        #pragma unroll
        for (int r = 0; r < 2; r++) {
            int t4 = tid + 256 * r;
            int m  = t4 >> 2;
            int k4 = (t4 & 3) * 4;
            float4 v = *(const float4*)(g_ctx + (size_t)(m0 + m) * HP + kc + k4);
            sA[k4 + 0][m] = v.x; sA[k4 + 1][m] = v.y;
            sA[k4 + 2][m] = v.z; sA[k4 + 3][m] = v.w;
        }
        #pragma unroll
        for (int r = 0; r < 2; r++) {
            int t4 = tid + 256 * r;
            int k  = t4 >> 5;
            int n4 = (t4 & 31) * 4;
            float4 v = *(const float4*)(g_dw + (size_t)(kc + k) * HP + n4);
            *(float4*)&sB[k][n4] = v;
        }
        __syncthreads();
        #pragma unroll
        for (int k = 0; k < 16; k++) {
            float a[8], b[8];
            #pragma unroll
            for (int i = 0; i < 8; i++) a[i] = sA[k][ty * 8 + i];
            #pragma unroll
            for (int j = 0; j < 8; j++) b[j] = sB[k][tx * 8 + j];
            #pragma unroll
            for (int i = 0; i < 8; i++)
                #pragma unroll
                for (int j = 0; j < 8; j++)
                    acc[i][j] = fmaf(a[i], b[j], acc[i][j]);
        }
        __syncthreads();
    }
    // write trans, accumulate norm partials
    float pn[8] = {};
    #pragma unroll
    for (int i = 0; i < 8; i++) {
        int m = m0 + ty * 8 + i;
        #pragma unroll
        for (int j = 0; j < 8; j++) {
            int n = tx * 8 + j;
            float v = acc[i][j];                       // exactly 0 for n>=120
            g_trans[(size_t)m * HP + n] = v;
            pn[i] = fmaf(v, g_ctx[(size_t)m * HP + n], pn[i]);
        }
    }
    #pragma unroll
    for (int i = 0; i < 8; i++) atomicAdd(&snorm[ty * 8 + i], pn[i]);
    __syncthreads();
    if (tid < 128) g_norm[m0 + tid] = snorm[tid];
}

// ---------------------------------------------------------
// Kernel: per batch, G = trans @ ctx^T (K=128), then
// e = exp(exp(-0.5*scale*(ni+nj-2G))) -> out (unnormalized),
// rowsum accumulated via shared + global atomics.
// grid (L/128, L/128, B)
// ---------------------------------------------------------
__global__ __launch_bounds__(256) void k_scores(const float* __restrict__ pinv,
                                                float* __restrict__ out) {
    __shared__ float sA[16][132];
    __shared__ float sB[16][132];
    __shared__ float srow[128];
    const int b  = blockIdx.z;
    const int i0 = blockIdx.y * 128;
    const int j0 = blockIdx.x * 128;
    const float* A  = g_trans + (size_t)b * LL * HP;
    const float* Bm = g_ctx   + (size_t)b * LL * HP;
    const int tid = threadIdx.x;
    const int tx = tid & 15, ty = tid >> 4;
    float acc[8][8] = {};
    if (tid < 128) srow[tid] = 0.0f;

    for (int kc = 0; kc < HP; kc += 16) {
        #pragma unroll
        for (int r = 0; r < 2; r++) {
            int t4 = tid + 256 * r;
            int m  = t4 >> 2;
            int k4 = (t4 & 3) * 4;
            float4 v = *(const float4*)(A + (size_t)(i0 + m) * HP + kc + k4);
            sA[k4 + 0][m] = v.x; sA[k4 + 1][m] = v.y;
            sA[k4 + 2][m] = v.z; sA[k4 + 3][m] = v.w;
        }
        #pragma unroll
        for (int r = 0; r < 2; r++) {
            int t4 = tid + 256 * r;
            int n  = t4 >> 2;
            int k4 = (t4 & 3) * 4;
            float4 v = *(const float4*)(Bm + (size_t)(j0 + n) * HP + kc + k4);
            sB[k4 + 0][n] = v.x; sB[k4 + 1][n] = v.y;
            sB[k4 + 2][n] = v.z; sB[k4 + 3][n] = v.w;
        }
        __syncthreads();
        #pragma unroll
        for (int k = 0; k < 16; k++) {
            float a[8], bb[8];
            #pragma unroll
            for (int i = 0; i < 8; i++) a[i] = sA[k][ty * 8 + i];
            #pragma unroll
            for (int j = 0; j < 8; j++) bb[j] = sB[k][tx * 8 + j];
            #pragma unroll
            for (int i = 0; i < 8; i++)
                #pragma unroll
                for (int j = 0; j < 8; j++)
                    acc[i][j] = fmaf(a[i], bb[j], acc[i][j]);
        }
        __syncthreads();
    }

    const float pv = pinv[0];
    const float sc = 0.5f * pv * pv;
    float ni[8], nj[8];
    #pragma unroll
    for (int i = 0; i < 8; i++) ni[i] = g_norm[(size_t)b * LL + i0 + ty * 8 + i];
    #pragma unroll
    for (int j = 0; j < 8; j++) nj[j] = g_norm[(size_t)b * LL + j0 + tx * 8 + j];

    float rs[8] = {};
    #pragma unroll
    for (int i = 0; i < 8; i++) {
        float ev[8];
        #pragma unroll
        for (int j = 0; j < 8; j++) {
            float d = ni[i] + nj[j] - 2.0f * acc[i][j];
            float s = __expf(-sc * d);     // RBF score in (0, ~1]
            float e = __expf(s);           // softmax numerator
            ev[j] = e;
            rs[i] += e;
        }
        size_t base = ((size_t)b * LL + i0 + ty * 8 + i) * LL + j0 + tx * 8;
        *(float4*)(out + base)     = make_float4(ev[0], ev[1], ev[2], ev[3]);
        *(float4*)(out + base + 4) = make_float4(ev[4], ev[5], ev[6], ev[7]);
    }
    #pragma unroll
    for (int i = 0; i < 8; i++) atomicAdd(&srow[ty * 8 + i], rs[i]);
    __syncthreads();
    if (tid < 128) atomicAdd(&g_rowsum[(size_t)b * LL + i0 + tid], srow[tid]);
}

// ---------------------------------------------------------
// Kernel: out /= rowsum (streaming, float4); LL/4 = 512 = 2^9
// ---------------------------------------------------------
__global__ void k_norm(float* __restrict__ out) {
    size_t idx = (size_t)blockIdx.x * blockDim.x + threadIdx.x;  // float4 index
    const size_t total4 = (size_t)M_TOTAL * LL / 4;
    if (idx < total4) {
        size_t row = idx >> 9;             // idx / (LL/4)
        float r = 1.0f / g_rowsum[row];
        float4 v = ((const float4*)out)[idx];
        v.x *= r; v.y *= r; v.z *= r; v.w *= r;
        ((float4*)out)[idx] = v;
    }
}

// ---------------------------------------------------------
extern "C" void kernel_launch(void* const* d_in, const int* in_sizes, int n_in,
                              void* d_out, int out_size) {
    const float* Q    = (const float*)d_in[0];   // [8,2048,1024]
    // d_in[1] = key (unused by the reference)
    const float* qw   = (const float*)d_in[2];   // [120,1024]
    const float* qb   = (const float*)d_in[3];   // [120]
    const float* W    = (const float*)d_in[4];   // [120,120]
    const float* pinv = (const float*)d_in[5];   // [1,1]
    float* out = (float*)d_out;                  // [8,2048,2048] fp32

    k_zero<<<(M_TOTAL + 255) / 256, 256>>>();
    k_dw<<<128, 128>>>(W);
    k_ctx<<<M_TOTAL / 128, 256>>>(Q, qw, qb);
    k_trans<<<M_TOTAL / 128, 256>>>();
    dim3 gs(LL / 128, LL / 128, BB);
    k_scores<<<gs, 256>>>(pinv, out);
    size_t total4 = (size_t)M_TOTAL * LL / 4;
    k_norm<<<(unsigned)((total4 + 255) / 256), 256>>>(out);
}

// round 4
// speedup vs baseline: 1.0582x; 1.0582x over previous
#include <cuda_runtime.h>
#include <cstdint>
#include <cstddef>

// Problem dims (fixed by the reference)
#define BB 8
#define LL 2048
#define DM 1024
#define HD 120
#define HP 128            // H padded to 128 with exact zeros
#define M_TOTAL (BB*LL)   // 16384

typedef unsigned long long ull;

// Packed fp32x2 FMA: acc.{lo,hi} += a.{lo,hi} * b.{lo,hi}
#define FMA2(acc, a, b) \
    asm("fma.rn.f32x2 %0, %1, %2, %0;" : "+l"(acc) : "l"(a), "l"(b))
#define UNPACK2(lo, hi, v) \
    asm("mov.b64 {%0, %1}, %2;" : "=f"(lo), "=f"(hi) : "l"(v))

// -------- device scratch (no allocations allowed) --------
__device__ float g_ctx[M_TOTAL * HP];     // 8 MB, cols >=120 are 0
__device__ float g_trans[M_TOTAL * HP];   // 8 MB, cols >=120 are 0
__device__ float g_norm[M_TOTAL];
__device__ float g_rowsum[M_TOTAL];
__device__ float g_dw[HP * HP];           // W@W^T padded with zeros (symmetric)

// ---------------------------------------------------------
__global__ void k_zero() {
    int i = blockIdx.x * blockDim.x + threadIdx.x;
    if (i < M_TOTAL) g_rowsum[i] = 0.0f;
}

// ---------------------------------------------------------
// DW = W @ W^T, padded to 128x128 with zeros
// ---------------------------------------------------------
__global__ void k_dw(const float* __restrict__ W) {
    __shared__ float sw[HP];
    int i = blockIdx.x;     // output row
    int t = threadIdx.x;    // output col
    sw[t] = (i < HD && t < HD) ? W[i * HD + t] : 0.0f;
    __syncthreads();
    float acc = 0.0f;
    if (i < HD && t < HD) {
        const float* wr = W + t * HD;
        #pragma unroll 8
        for (int k = 0; k < HD; k++) acc = fmaf(sw[k], wr[k], acc);
    }
    g_dw[i * HP + t] = acc;
}

// ---------------------------------------------------------
// ctx[16384,128] = Q[16384,1024] @ qw^T + bias (cols>=120 -> 0)
// 64x128 tile, 256 threads, 4x8 microtile, k-pair FFMA2, Kc=16
// grid = 256 blocks
// ---------------------------------------------------------
__global__ __launch_bounds__(256) void k_ctx(const float* __restrict__ Q,
                                             const float* __restrict__ qw,
                                             const float* __restrict__ qb) {
    __shared__ float2 sA[8][65];     // [kk][m]  k-pairs, 64 rows (+1 pad)
    __shared__ float2 sB[8][129];    // [kk][n]  k-pairs, 128 rows (+1 pad)
    const int m0 = blockIdx.x * 64;
    const int tid = threadIdx.x;
    const int tx = tid & 15, ty = tid >> 4;
    ull acc[4][8] = {};

    for (int kc = 0; kc < DM; kc += 16) {
        // A: 64 rows x 16 k = 256 float4, 1 per thread
        {
            int m  = tid >> 2;
            int k4 = (tid & 3) * 4;
            int kk = (tid & 3) * 2;
            float4 v = *(const float4*)(Q + (size_t)(m0 + m) * DM + kc + k4);
            sA[kk][m]     = make_float2(v.x, v.y);
            sA[kk + 1][m] = make_float2(v.z, v.w);
        }
        // B: 128 rows x 16 k = 512 float4, 2 per thread (zero-pad n>=120)
        #pragma unroll
        for (int r2 = 0; r2 < 2; r2++) {
            int t4 = tid + 256 * r2;
            int n  = t4 >> 2;
            int k4 = (t4 & 3) * 4;
            int kk = (t4 & 3) * 2;
            float4 v = make_float4(0.f, 0.f, 0.f, 0.f);
            if (n < HD) v = *(const float4*)(qw + (size_t)n * DM + kc + k4);
            sB[kk][n]     = make_float2(v.x, v.y);
            sB[kk + 1][n] = make_float2(v.z, v.w);
        }
        __syncthreads();
        #pragma unroll
        for (int kk = 0; kk < 8; kk++) {
            ull a2[4], b2[8];
            #pragma unroll
            for (int r = 0; r < 4; r++) a2[r] = *(const ull*)&sA[kk][ty + r * 16];
            #pragma unroll
            for (int c = 0; c < 8; c++) b2[c] = *(const ull*)&sB[kk][tx + c * 16];
            #pragma unroll
            for (int r = 0; r < 4; r++)
                #pragma unroll
                for (int c = 0; c < 8; c++)
                    FMA2(acc[r][c], a2[r], b2[c]);
        }
        __syncthreads();
    }
    #pragma unroll
    for (int r = 0; r < 4; r++) {
        int m = m0 + ty + r * 16;
        #pragma unroll
        for (int c = 0; c < 8; c++) {
            int n = tx + c * 16;
            float lo, hi; UNPACK2(lo, hi, acc[r][c]);
            float v = (n < HD) ? (lo + hi + qb[n]) : 0.0f;
            g_ctx[(size_t)m * HP + n] = v;
        }
    }
}

// ---------------------------------------------------------
// trans = ctx @ DW (K=128) + norm[m] = sum(trans*ctx)
// 64x128 tile, 256 threads, 4x8 microtile, k-pair FFMA2
// grid = 256 blocks; norm via warp shuffles (no atomics)
// ---------------------------------------------------------
__global__ __launch_bounds__(256) void k_trans() {
    __shared__ float2 sA[8][65];
    __shared__ float2 sB[8][129];
    const int m0 = blockIdx.x * 64;
    const int tid = threadIdx.x;
    const int tx = tid & 15, ty = tid >> 4;
    ull acc[4][8] = {};

    for (int kc = 0; kc < HP; kc += 16) {
        {
            int m  = tid >> 2;
            int k4 = (tid & 3) * 4;
            int kk = (tid & 3) * 2;
            float4 v = *(const float4*)(g_ctx + (size_t)(m0 + m) * HP + kc + k4);
            sA[kk][m]     = make_float2(v.x, v.y);
            sA[kk + 1][m] = make_float2(v.z, v.w);
        }
        #pragma unroll
        for (int r2 = 0; r2 < 2; r2++) {
            int t4 = tid + 256 * r2;
            int n  = t4 >> 2;
            int k4 = (t4 & 3) * 4;
            int kk = (t4 & 3) * 2;
            // DW is symmetric; row n over k
            float4 v = *(const float4*)(g_dw + (size_t)n * HP + kc + k4);
            sB[kk][n]     = make_float2(v.x, v.y);
            sB[kk + 1][n] = make_float2(v.z, v.w);
        }
        __syncthreads();
        #pragma unroll
        for (int kk = 0; kk < 8; kk++) {
            ull a2[4], b2[8];
            #pragma unroll
            for (int r = 0; r < 4; r++) a2[r] = *(const ull*)&sA[kk][ty + r * 16];
            #pragma unroll
            for (int c = 0; c < 8; c++) b2[c] = *(const ull*)&sB[kk][tx + c * 16];
            #pragma unroll
            for (int r = 0; r < 4; r++)
                #pragma unroll
                for (int c = 0; c < 8; c++)
                    FMA2(acc[r][c], a2[r], b2[c]);
        }
        __syncthreads();
    }
    // epilogue: write trans, accumulate norm partials, shfl-reduce
    float pn[4] = {};
    #pragma unroll
    for (int r = 0; r < 4; r++) {
        int m = m0 + ty + r * 16;
        #pragma unroll
        for (int c = 0; c < 8; c++) {
            int n = tx + c * 16;
            float lo, hi; UNPACK2(lo, hi, acc[r][c]);
            float v = lo + hi;                       // exact 0 for n>=120
            g_trans[(size_t)m * HP + n] = v;
            pn[r] = fmaf(v, g_ctx[(size_t)m * HP + n], pn[r]);
        }
    }
    #pragma unroll
    for (int r = 0; r < 4; r++) {
        float s = pn[r];
        #pragma unroll
        for (int m2 = 8; m2 >= 1; m2 >>= 1)
            s += __shfl_xor_sync(0xffffffffu, s, m2);
        if (tx == 0) g_norm[m0 + ty + r * 16] = s;   // complete (block covers all cols)
    }
}

// ---------------------------------------------------------
// per batch: G = trans @ ctx^T (K=128), e = exp(exp(-0.5*scale*(ni+nj-2G)))
// -> out (unnormalized); rowsum via shfl + global atomics.
// 128x128 tile, 256 threads, 8x8 microtile, k-pair FFMA2
// grid (L/128, L/128, B) = 2048 blocks
// ---------------------------------------------------------
__global__ __launch_bounds__(256) void k_scores(const float* __restrict__ pinv,
                                                float* __restrict__ out) {
    __shared__ float2 sA[8][129];
    __shared__ float2 sB[8][129];
    const int b  = blockIdx.z;
    const int i0 = blockIdx.y * 128;
    const int j0 = blockIdx.x * 128;
    const float* A  = g_trans + (size_t)b * LL * HP;
    const float* Bm = g_ctx   + (size_t)b * LL * HP;
    const int tid = threadIdx.x;
    const int tx = tid & 15, ty = tid >> 4;
    ull acc[8][8] = {};

    for (int kc = 0; kc < HP; kc += 16) {
        #pragma unroll
        for (int r2 = 0; r2 < 2; r2++) {
            int t4 = tid + 256 * r2;
            int m  = t4 >> 2;
            int k4 = (t4 & 3) * 4;
            int kk = (t4 & 3) * 2;
            float4 v = *(const float4*)(A + (size_t)(i0 + m) * HP + kc + k4);
            sA[kk][m]     = make_float2(v.x, v.y);
            sA[kk + 1][m] = make_float2(v.z, v.w);
        }
        #pragma unroll
        for (int r2 = 0; r2 < 2; r2++) {
            int t4 = tid + 256 * r2;
            int n  = t4 >> 2;
            int k4 = (t4 & 3) * 4;
            int kk = (t4 & 3) * 2;
            float4 v = *(const float4*)(Bm + (size_t)(j0 + n) * HP + kc + k4);
            sB[kk][n]     = make_float2(v.x, v.y);
            sB[kk + 1][n] = make_float2(v.z, v.w);
        }
        __syncthreads();
        #pragma unroll
        for (int kk = 0; kk < 8; kk++) {
            ull a2[8], b2[8];
            #pragma unroll
            for (int r = 0; r < 8; r++) a2[r] = *(const ull*)&sA[kk][ty + r * 16];
            #pragma unroll
            for (int c = 0; c < 8; c++) b2[c] = *(const ull*)&sB[kk][tx + c * 16];
            #pragma unroll
            for (int r = 0; r < 8; r++)
                #pragma unroll
                for (int c = 0; c < 8; c++)
                    FMA2(acc[r][c], a2[r], b2[c]);
        }
        __syncthreads();
    }

    const float pv = pinv[0];
    const float sc = 0.5f * pv * pv;
    float ni[8], nj[8];
    #pragma unroll
    for (int r = 0; r < 8; r++) ni[r] = g_norm[(size_t)b * LL + i0 + ty + r * 16];
    #pragma unroll
    for (int c = 0; c < 8; c++) nj[c] = g_norm[(size_t)b * LL + j0 + tx + c * 16];

    #pragma unroll
    for (int r = 0; r < 8; r++) {
        int i = i0 + ty + r * 16;
        float rs = 0.0f;
        #pragma unroll
        for (int c = 0; c < 8; c++) {
            int j = j0 + tx + c * 16;
            float lo, hi; UNPACK2(lo, hi, acc[r][c]);
            float d = ni[r] + nj[c] - 2.0f * (lo + hi);
            float s = __expf(-sc * d);     // RBF score
            float e = __expf(s);           // softmax numerator
            rs += e;
            out[((size_t)b * LL + i) * LL + j] = e;
        }
        // reduce rs over the 16 tx lanes (bits 0..3 of lane id)
        #pragma unroll
        for (int m2 = 8; m2 >= 1; m2 >>= 1)
            rs += __shfl_xor_sync(0xffffffffu, rs, m2);
        if (tx == 0) atomicAdd(&g_rowsum[(size_t)b * LL + i], rs);
    }
}

// ---------------------------------------------------------
// out /= rowsum (streaming, float4); LL/4 = 512 = 2^9
// ---------------------------------------------------------
__global__ void k_norm(float* __restrict__ out) {
    size_t idx = (size_t)blockIdx.x * blockDim.x + threadIdx.x;  // float4 index
    const size_t total4 = (size_t)M_TOTAL * LL / 4;
    if (idx < total4) {
        size_t row = idx >> 9;             // idx / (LL/4)
        float r = 1.0f / g_rowsum[row];
        float4 v = ((const float4*)out)[idx];
        v.x *= r; v.y *= r; v.z *= r; v.w *= r;
        ((float4*)out)[idx] = v;
    }
}

// ---------------------------------------------------------
extern "C" void kernel_launch(void* const* d_in, const int* in_sizes, int n_in,
                              void* d_out, int out_size) {
    const float* Q    = (const float*)d_in[0];   // [8,2048,1024]
    // d_in[1] = key (unused by the reference)
    const float* qw   = (const float*)d_in[2];   // [120,1024]
    const float* qb   = (const float*)d_in[3];   // [120]
    const float* W    = (const float*)d_in[4];   // [120,120]
    const float* pinv = (const float*)d_in[5];   // [1,1]
    float* out = (float*)d_out;                  // [8,2048,2048] fp32

    k_zero<<<(M_TOTAL + 255) / 256, 256>>>();
    k_dw<<<128, 128>>>(W);
    k_ctx<<<M_TOTAL / 64, 256>>>(Q, qw, qb);
    k_trans<<<M_TOTAL / 64, 256>>>();
    dim3 gs(LL / 128, LL / 128, BB);
    k_scores<<<gs, 256>>>(pinv, out);
    size_t total4 = (size_t)M_TOTAL * LL / 4;
    k_norm<<<(unsigned)((total4 + 255) / 256), 256>>>(out);
}

// round 8
// speedup vs baseline: 1.3571x; 1.2824x over previous
#include <cuda_runtime.h>
#include <cuda_bf16.h>
#include <cstdint>
#include <cstddef>

// Problem dims (fixed by the reference)
#define BB 8
#define LL 2048
#define DM 1024
#define HD 120
#define HP 128            // H padded to 128 with exact zeros
#define M_TOTAL (BB*LL)   // 16384

typedef unsigned long long ull;

// Packed fp32x2 FMA (baseline PTX, works on sm_100)
#define FMA2(acc, a, b) \
    asm("fma.rn.f32x2 %0, %1, %2, %0;" : "+l"(acc) : "l"(a), "l"(b))
#define UNPACK2(lo, hi, v) \
    asm("mov.b64 {%0, %1}, %2;" : "=f"(lo), "=f"(hi) : "l"(v))

// Warp-level tensor-core MMA (sm_80+ baseline: HMMA.16816, bf16 in / f32 acc)
#define MMA16816(c, a, b0, b1) \
    asm volatile("mma.sync.aligned.m16n8k16.row.col.f32.bf16.bf16.f32 " \
        "{%0,%1,%2,%3}, {%4,%5,%6,%7}, {%8,%9}, {%0,%1,%2,%3};" \
        : "+f"((c)[0]), "+f"((c)[1]), "+f"((c)[2]), "+f"((c)[3]) \
        : "r"((a)[0]), "r"((a)[1]), "r"((a)[2]), "r"((a)[3]), "r"(b0), "r"(b1))

// -------- device scratch (no allocations allowed) --------
__device__ float g_ctx[M_TOTAL * HP];         // fp32 ctx (cols>=120 zero)
__device__ float g_norm[M_TOTAL];
__device__ float g_rowsum[M_TOTAL];
__device__ float g_dw[HP * HP];               // W@W^T padded (symmetric)
// bf16 split-precision copies (16B-vector loaded -> force alignment)
__device__ alignas(256) __nv_bfloat16 g_ctx_hi[M_TOTAL * HP];
__device__ alignas(256) __nv_bfloat16 g_ctx_lo[M_TOTAL * HP];
__device__ alignas(256) __nv_bfloat16 g_tr_hi[M_TOTAL * HP];
__device__ alignas(256) __nv_bfloat16 g_tr_lo[M_TOTAL * HP];

// ---------------------------------------------------------
__global__ void k_zero() {
    int i = blockIdx.x * blockDim.x + threadIdx.x;
    if (i < M_TOTAL) g_rowsum[i] = 0.0f;
}

// ---------------------------------------------------------
__global__ void k_dw(const float* __restrict__ W) {
    __shared__ float sw[HP];
    int i = blockIdx.x, t = threadIdx.x;
    sw[t] = (i < HD && t < HD) ? W[i * HD + t] : 0.0f;
    __syncthreads();
    float acc = 0.0f;
    if (i < HD && t < HD) {
        const float* wr = W + t * HD;
        #pragma unroll 8
        for (int k = 0; k < HD; k++) acc = fmaf(sw[k], wr[k], acc);
    }
    g_dw[i * HP + t] = acc;
}

// ---------------------------------------------------------
// ctx = Q @ qw^T + bias; writes fp32 + bf16 hi/lo split
// ---------------------------------------------------------
__global__ __launch_bounds__(256) void k_ctx(const float* __restrict__ Q,
                                             const float* __restrict__ qw,
                                             const float* __restrict__ qb) {
    __shared__ float2 sA[8][65];
    __shared__ float2 sB[8][129];
    const int m0 = blockIdx.x * 64;
    const int tid = threadIdx.x;
    const int tx = tid & 15, ty = tid >> 4;
    ull acc[4][8] = {};

    for (int kc = 0; kc < DM; kc += 16) {
        {
            int m  = tid >> 2;
            int k4 = (tid & 3) * 4;
            int kk = (tid & 3) * 2;
            float4 v = *(const float4*)(Q + (size_t)(m0 + m) * DM + kc + k4);
            sA[kk][m]     = make_float2(v.x, v.y);
            sA[kk + 1][m] = make_float2(v.z, v.w);
        }
        #pragma unroll
        for (int r2 = 0; r2 < 2; r2++) {
            int t4 = tid + 256 * r2;
            int n  = t4 >> 2;
            int k4 = (t4 & 3) * 4;
            int kk = (t4 & 3) * 2;
            float4 v = make_float4(0.f, 0.f, 0.f, 0.f);
            if (n < HD) v = *(const float4*)(qw + (size_t)n * DM + kc + k4);
            sB[kk][n]     = make_float2(v.x, v.y);
            sB[kk + 1][n] = make_float2(v.z, v.w);
        }
        __syncthreads();
        #pragma unroll
        for (int kk = 0; kk < 8; kk++) {
            ull a2[4], b2[8];
            #pragma unroll
            for (int r = 0; r < 4; r++) a2[r] = *(const ull*)&sA[kk][ty + r * 16];
            #pragma unroll
            for (int c = 0; c < 8; c++) b2[c] = *(const ull*)&sB[kk][tx + c * 16];
            #pragma unroll
            for (int r = 0; r < 4; r++)
                #pragma unroll
                for (int c = 0; c < 8; c++)
                    FMA2(acc[r][c], a2[r], b2[c]);
        }
        __syncthreads();
    }
    #pragma unroll
    for (int r = 0; r < 4; r++) {
        int m = m0 + ty + r * 16;
        #pragma unroll
        for (int c = 0; c < 8; c++) {
            int n = tx + c * 16;
            float lo, hi; UNPACK2(lo, hi, acc[r][c]);
            float v = (n < HD) ? (lo + hi + qb[n]) : 0.0f;
            size_t idx = (size_t)m * HP + n;
            g_ctx[idx] = v;
            __nv_bfloat16 vh = __float2bfloat16(v);
            g_ctx_hi[idx] = vh;
            g_ctx_lo[idx] = __float2bfloat16(v - __bfloat162float(vh));
        }
    }
}

// ---------------------------------------------------------
// trans = ctx @ DW (K=128) -> bf16 hi/lo; norm = sum(trans*ctx)
// ---------------------------------------------------------
__global__ __launch_bounds__(256) void k_trans() {
    __shared__ float2 sA[8][65];
    __shared__ float2 sB[8][129];
    const int m0 = blockIdx.x * 64;
    const int tid = threadIdx.x;
    const int tx = tid & 15, ty = tid >> 4;
    ull acc[4][8] = {};

    for (int kc = 0; kc < HP; kc += 16) {
        {
            int m  = tid >> 2;
            int k4 = (tid & 3) * 4;
            int kk = (tid & 3) * 2;
            float4 v = *(const float4*)(g_ctx + (size_t)(m0 + m) * HP + kc + k4);
            sA[kk][m]     = make_float2(v.x, v.y);
            sA[kk + 1][m] = make_float2(v.z, v.w);
        }
        #pragma unroll
        for (int r2 = 0; r2 < 2; r2++) {
            int t4 = tid + 256 * r2;
            int n  = t4 >> 2;
            int k4 = (t4 & 3) * 4;
            int kk = (t4 & 3) * 2;
            float4 v = *(const float4*)(g_dw + (size_t)n * HP + kc + k4);
            sB[kk][n]     = make_float2(v.x, v.y);
            sB[kk + 1][n] = make_float2(v.z, v.w);
        }
        __syncthreads();
        #pragma unroll
        for (int kk = 0; kk < 8; kk++) {
            ull a2[4], b2[8];
            #pragma unroll
            for (int r = 0; r < 4; r++) a2[r] = *(const ull*)&sA[kk][ty + r * 16];
            #pragma unroll
            for (int c = 0; c < 8; c++) b2[c] = *(const ull*)&sB[kk][tx + c * 16];
            #pragma unroll
            for (int r = 0; r < 4; r++)
                #pragma unroll
                for (int c = 0; c < 8; c++)
                    FMA2(acc[r][c], a2[r], b2[c]);
        }
        __syncthreads();
    }
    float pn[4] = {};
    #pragma unroll
    for (int r = 0; r < 4; r++) {
        int m = m0 + ty + r * 16;
        #pragma unroll
        for (int c = 0; c < 8; c++) {
            int n = tx + c * 16;
            float lo, hi; UNPACK2(lo, hi, acc[r][c]);
            float v = lo + hi;                       // exact 0 for n>=120
            size_t idx = (size_t)m * HP + n;
            __nv_bfloat16 vh = __float2bfloat16(v);
            g_tr_hi[idx] = vh;
            g_tr_lo[idx] = __float2bfloat16(v - __bfloat162float(vh));
            pn[r] = fmaf(v, g_ctx[idx], pn[r]);
        }
    }
    #pragma unroll
    for (int r = 0; r < 4; r++) {
        float s = pn[r];
        #pragma unroll
        for (int m2 = 8; m2 >= 1; m2 >>= 1)
            s += __shfl_xor_sync(0xffffffffu, s, m2);
        if (tx == 0) g_norm[m0 + ty + r * 16] = s;
    }
}

// ---------------------------------------------------------
// Tensor-core scores via mma.sync (HMMA.16816 bf16):
// G = trans @ ctx^T, split-precision 3-pass (AhBh + AhBl + AlBh),
// fused double-exp + rowsum + smem-staged coalesced stores.
// grid (16,16,8), 256 threads = 8 warps in a 4(m) x 2(n) grid;
// warp tile 32x64, thread frags per mma.sync m16n8k16 layout.
// ---------------------------------------------------------
#define TS       144                  // smem tile row pitch (bytes): 64 bf16 + 8 pad
#define TILE_B   (128 * TS)           // 18432 B per tile
#define SC_SROW  16                   // 128 f32 rowsum partials
#define SC_SNI   544                  // 128 f32 norm_i
#define SC_SNJ   1072                 // 128 f32 norm_j
#define SC_AH    2048
#define SC_AL    (SC_AH + TILE_B)
#define SC_BH    (SC_AL + TILE_B)
#define SC_BL    (SC_BH + TILE_B)
#define SC_SMEM_TOTAL (SC_BL + TILE_B)        // 75776
#define SC_OUT   2048                 // epilogue staging reuses tile region
#define OUT_P    130                  // staging pitch (floats): even -> aligned float2

__global__ __launch_bounds__(256) void k_scores_mma(const float* __restrict__ pinv,
                                                    float* __restrict__ out) {
    extern __shared__ char smem[];
    const int tid  = threadIdx.x;
    const int wid  = tid >> 5, lane = tid & 31;
    const int gid  = lane >> 2, tig = lane & 3;
    const int wm   = wid & 3;          // warp row   (0..3)  -> rows 32*wm
    const int wn   = wid >> 2;         // warp col   (0..1)  -> cols 64*wn
    const int b  = blockIdx.z;
    const int i0 = blockIdx.y * 128;
    const int j0 = blockIdx.x * 128;

    const __nv_bfloat16* Ah = g_tr_hi  + (size_t)b * LL * HP;
    const __nv_bfloat16* Al = g_tr_lo  + (size_t)b * LL * HP;
    const __nv_bfloat16* Bh = g_ctx_hi + (size_t)b * LL * HP;
    const __nv_bfloat16* Bl = g_ctx_lo + (size_t)b * LL * HP;

    if (tid < 128) {
        *(float*)(smem + SC_SROW + tid * 4) = 0.0f;
        *(float*)(smem + SC_SNI  + tid * 4) = g_norm[(size_t)b * LL + i0 + tid];
        *(float*)(smem + SC_SNJ  + tid * 4) = g_norm[(size_t)b * LL + j0 + tid];
    }

    float acc[2][8][4] = {};       // [mt][nt][c0,c1,c2,c3]

    #pragma unroll 1
    for (int ch = 0; ch < 2; ch++) {
        __syncthreads();           // tiles free (prev chunk mma done / first entry)
        // load 4 tiles [128 x 64 bf16] into padded rows (16 uint4 per thread)
        #pragma unroll
        for (int it = 0; it < 4; it++) {
            int t = tid + it * 256;               // 0..1023
            int row = t >> 3, g = t & 7;
            uint32_t dst = (uint32_t)row * TS + g * 16;
            size_t sa = (size_t)(i0 + row) * HP + ch * 64 + g * 8;
            size_t sb2 = (size_t)(j0 + row) * HP + ch * 64 + g * 8;
            *(uint4*)(smem + SC_AH + dst) = *(const uint4*)(Ah + sa);
            *(uint4*)(smem + SC_AL + dst) = *(const uint4*)(Al + sa);
            *(uint4*)(smem + SC_BH + dst) = *(const uint4*)(Bh + sb2);
            *(uint4*)(smem + SC_BL + dst) = *(const uint4*)(Bl + sb2);
        }
        __syncthreads();

        #pragma unroll
        for (int ks = 0; ks < 4; ks++) {
            // A fragments (conflict-free: pitch 144B -> bank = 4*gid + tig)
            uint32_t ah[2][4], al[2][4];
            uint32_t abase = (uint32_t)(wm * 32 + gid) * TS + tig * 4 + ks * 32;
            #pragma unroll
            for (int mt = 0; mt < 2; mt++) {
                uint32_t o = abase + mt * (16 * TS);
                ah[mt][0] = *(const uint32_t*)(smem + SC_AH + o);
                ah[mt][1] = *(const uint32_t*)(smem + SC_AH + o + 8 * TS);
                ah[mt][2] = *(const uint32_t*)(smem + SC_AH + o + 16);
                ah[mt][3] = *(const uint32_t*)(smem + SC_AH + o + 8 * TS + 16);
                al[mt][0] = *(const uint32_t*)(smem + SC_AL + o);
                al[mt][1] = *(const uint32_t*)(smem + SC_AL + o + 8 * TS);
                al[mt][2] = *(const uint32_t*)(smem + SC_AL + o + 16);
                al[mt][3] = *(const uint32_t*)(smem + SC_AL + o + 8 * TS + 16);
            }
            #pragma unroll
            for (int nt = 0; nt < 8; nt++) {
                uint32_t bbase = (uint32_t)(wn * 64 + nt * 8 + gid) * TS + tig * 4 + ks * 32;
                uint32_t bh0 = *(const uint32_t*)(smem + SC_BH + bbase);
                uint32_t bh1 = *(const uint32_t*)(smem + SC_BH + bbase + 16);
                uint32_t bl0 = *(const uint32_t*)(smem + SC_BL + bbase);
                uint32_t bl1 = *(const uint32_t*)(smem + SC_BL + bbase + 16);
                #pragma unroll
                for (int mt = 0; mt < 2; mt++) {
                    MMA16816(acc[mt][nt], ah[mt], bh0, bh1);   // Ah*Bh
                    MMA16816(acc[mt][nt], ah[mt], bl0, bl1);   // Ah*Bl
                    MMA16816(acc[mt][nt], al[mt], bh0, bh1);   // Al*Bh
                }
            }
        }
    }
    __syncthreads();   // mma done -> staging region reusable

    const float pv = pinv[0];
    const float sc = 0.5f * pv * pv;

    #pragma unroll
    for (int mt = 0; mt < 2; mt++) {
        #pragma unroll
        for (int rh = 0; rh < 2; rh++) {
            int row = wm * 32 + mt * 16 + rh * 8 + gid;
            float ni = *(const float*)(smem + SC_SNI + row * 4);
            float rs = 0.0f;
            #pragma unroll
            for (int nt = 0; nt < 8; nt++) {
                int col = wn * 64 + nt * 8 + tig * 2;
                float nj0 = *(const float*)(smem + SC_SNJ + col * 4);
                float nj1 = *(const float*)(smem + SC_SNJ + col * 4 + 4);
                float g0 = acc[mt][nt][rh * 2 + 0];
                float g1 = acc[mt][nt][rh * 2 + 1];
                float e0 = __expf(__expf(-sc * (ni + nj0 - 2.0f * g0)));
                float e1 = __expf(__expf(-sc * (ni + nj1 - 2.0f * g1)));
                rs += e0 + e1;
                *(float2*)(smem + SC_OUT + (row * OUT_P + col) * 4) = make_float2(e0, e1);
            }
            rs += __shfl_xor_sync(0xffffffffu, rs, 1);
            rs += __shfl_xor_sync(0xffffffffu, rs, 2);
            if (tig == 0)
                atomicAdd((float*)(smem + SC_SROW + row * 4), rs);
        }
    }
    __syncthreads();
    if (tid < 128)
        atomicAdd(&g_rowsum[(size_t)b * LL + i0 + tid],
                  *(const float*)(smem + SC_SROW + tid * 4));

    // fully-coalesced store of the 128x128 tile
    #pragma unroll 8
    for (int it = 0; it < 64; it++) {
        int lin = it * 256 + tid;
        int row = lin >> 7, col = lin & 127;
        out[((size_t)b * LL + i0 + row) * LL + j0 + col] =
            *(const float*)(smem + SC_OUT + (row * OUT_P + col) * 4);
    }
}

// ---------------------------------------------------------
// out /= rowsum (streaming, float4)
// ---------------------------------------------------------
__global__ void k_norm(float* __restrict__ out) {
    size_t idx = (size_t)blockIdx.x * blockDim.x + threadIdx.x;
    const size_t total4 = (size_t)M_TOTAL * LL / 4;
    if (idx < total4) {
        size_t row = idx >> 9;
        float r = 1.0f / g_rowsum[row];
        float4 v = ((const float4*)out)[idx];
        v.x *= r; v.y *= r; v.z *= r; v.w *= r;
        ((float4*)out)[idx] = v;
    }
}

// ---------------------------------------------------------
extern "C" void kernel_launch(void* const* d_in, const int* in_sizes, int n_in,
                              void* d_out, int out_size) {
    const float* Q    = (const float*)d_in[0];
    const float* qw   = (const float*)d_in[2];
    const float* qb   = (const float*)d_in[3];
    const float* W    = (const float*)d_in[4];
    const float* pinv = (const float*)d_in[5];
    float* out = (float*)d_out;

    // idempotent, capture-legal; called every time (no static guards allowed)
    cudaFuncSetAttribute(k_scores_mma, cudaFuncAttributeMaxDynamicSharedMemorySize,
                         SC_SMEM_TOTAL);

    k_zero<<<(M_TOTAL + 255) / 256, 256>>>();
    k_dw<<<128, 128>>>(W);
    k_ctx<<<M_TOTAL / 64, 256>>>(Q, qw, qb);
    k_trans<<<M_TOTAL / 64, 256>>>();
    dim3 gs(LL / 128, LL / 128, BB);
    k_scores_mma<<<gs, 256, SC_SMEM_TOTAL>>>(pinv, out);
    size_t total4 = (size_t)M_TOTAL * LL / 4;
    k_norm<<<(unsigned)((total4 + 255) / 256), 256>>>(out);
}

// round 9
// speedup vs baseline: 1.7724x; 1.3060x over previous
#include <cuda_runtime.h>
#include <cuda_bf16.h>
#include <cstdint>
#include <cstddef>

// Problem dims (fixed by the reference)
#define BB 8
#define LL 2048
#define DM 1024
#define HD 120
#define HP 128            // H padded to 128 with exact zeros
#define M_TOTAL (BB*LL)   // 16384

typedef unsigned long long ull;

// Packed fp32x2 FMA (baseline PTX)
#define FMA2(acc, a, b) \
    asm("fma.rn.f32x2 %0, %1, %2, %0;" : "+l"(acc) : "l"(a), "l"(b))
#define UNPACK2(lo, hi, v) \
    asm("mov.b64 {%0, %1}, %2;" : "=f"(lo), "=f"(hi) : "l"(v))

// Warp-level tensor-core MMA (sm_80+ baseline: HMMA.16816, bf16 in / f32 acc)
#define MMA16816(c, a, b0, b1) \
    asm volatile("mma.sync.aligned.m16n8k16.row.col.f32.bf16.bf16.f32 " \
        "{%0,%1,%2,%3}, {%4,%5,%6,%7}, {%8,%9}, {%0,%1,%2,%3};" \
        : "+f"((c)[0]), "+f"((c)[1]), "+f"((c)[2]), "+f"((c)[3]) \
        : "r"((a)[0]), "r"((a)[1]), "r"((a)[2]), "r"((a)[3]), "r"(b0), "r"(b1))

__device__ __forceinline__ uint32_t pack_bf2(float x, float y) {
    return ((uint32_t)__bfloat16_as_ushort(__float2bfloat16(y)) << 16) |
           (uint32_t)__bfloat16_as_ushort(__float2bfloat16(x));
}

// -------- device scratch (no allocations allowed) --------
__device__ float g_ctx[M_TOTAL * HP];         // fp32 ctx (cols>=120 zero)
__device__ float g_norm[M_TOTAL];
__device__ float g_rowsum[M_TOTAL];
__device__ float g_dw[HP * HP];               // W@W^T padded (symmetric)
// bf16 split-precision copies (16B-vector loaded -> force alignment)
__device__ alignas(256) __nv_bfloat16 g_ctx_hi[M_TOTAL * HP];
__device__ alignas(256) __nv_bfloat16 g_ctx_lo[M_TOTAL * HP];
__device__ alignas(256) __nv_bfloat16 g_tr_hi[M_TOTAL * HP];
__device__ alignas(256) __nv_bfloat16 g_tr_lo[M_TOTAL * HP];
__device__ alignas(256) __nv_bfloat16 g_qw_hi[HP * DM];   // qw split, rows>=120 zero
__device__ alignas(256) __nv_bfloat16 g_qw_lo[HP * DM];

// ---------------------------------------------------------
__global__ void k_zero() {
    int i = blockIdx.x * blockDim.x + threadIdx.x;
    if (i < M_TOTAL) g_rowsum[i] = 0.0f;
}

// ---------------------------------------------------------
// qw -> bf16 hi/lo split (padded rows zero). 512 blocks x 256.
// ---------------------------------------------------------
__global__ void k_wsplit(const float* __restrict__ qw) {
    int idx = blockIdx.x * blockDim.x + threadIdx.x;   // 0..HP*DM-1
    int n = idx >> 10, k = idx & 1023;
    float v = (n < HD) ? qw[n * DM + k] : 0.0f;
    __nv_bfloat16 vh = __float2bfloat16(v);
    g_qw_hi[idx] = vh;
    g_qw_lo[idx] = __float2bfloat16(v - __bfloat162float(vh));
}

// ---------------------------------------------------------
__global__ void k_dw(const float* __restrict__ W) {
    __shared__ float sw[HP];
    int i = blockIdx.x, t = threadIdx.x;
    sw[t] = (i < HD && t < HD) ? W[i * HD + t] : 0.0f;
    __syncthreads();
    float acc = 0.0f;
    if (i < HD && t < HD) {
        const float* wr = W + t * HD;
        #pragma unroll 8
        for (int k = 0; k < HD; k++) acc = fmaf(sw[k], wr[k], acc);
    }
    g_dw[i * HP + t] = acc;
}

// ---------------------------------------------------------
// ctx = Q @ qw^T + bias via HMMA split-bf16 (3-pass).
// grid 256 CTAs x 256 thr; CTA = 64 rows x 128 cols; K=1024 in 16 chunks.
// Q converted fp32 -> hi/lo bf16 during smem staging.
// ---------------------------------------------------------
#define TS       144                  // smem row pitch (bytes): 64 bf16 + 8 pad
#define CX_AH    0
#define CX_AL    (64 * TS)            // 9216
#define CX_BH    (2 * 64 * TS)        // 18432
#define CX_BL    (CX_BH + 128 * TS)   // 36864
#define CX_SMEM  (CX_BL + 128 * TS)   // 55296

__global__ __launch_bounds__(256) void k_ctx_mma(const float* __restrict__ Q,
                                                 const float* __restrict__ qb) {
    extern __shared__ char csm[];
    const int tid = threadIdx.x;
    const int wid = tid >> 5, lane = tid & 31;
    const int gid = lane >> 2, tig = lane & 3;
    const int wm = wid & 1;            // 2 warp-rows  -> rows 32*wm
    const int wn = wid >> 1;           // 4 warp-cols  -> cols 32*wn
    const int m0 = blockIdx.x * 64;

    float acc[2][4][4] = {};           // [mt][nt][c]

    #pragma unroll 1
    for (int ch = 0; ch < 16; ch++) {
        __syncthreads();
        // A: 64x64 fp32 from Q, convert to hi/lo (4 float4 per thread)
        #pragma unroll
        for (int i = 0; i < 4; i++) {
            int t = tid + i * 256;                 // 0..1023
            int row = t >> 4, c4 = t & 15;
            float4 v = *(const float4*)(Q + (size_t)(m0 + row) * DM + ch * 64 + c4 * 4);
            uint32_t h0 = pack_bf2(v.x, v.y), h1 = pack_bf2(v.z, v.w);
            float rx = v.x - __bfloat162float(__ushort_as_bfloat16((unsigned short)(h0 & 0xFFFF)));
            float ry = v.y - __bfloat162float(__ushort_as_bfloat16((unsigned short)(h0 >> 16)));
            float rz = v.z - __bfloat162float(__ushort_as_bfloat16((unsigned short)(h1 & 0xFFFF)));
            float rw = v.w - __bfloat162float(__ushort_as_bfloat16((unsigned short)(h1 >> 16)));
            uint32_t l0 = pack_bf2(rx, ry), l1 = pack_bf2(rz, rw);
            *(uint2*)(csm + CX_AH + row * TS + c4 * 8) = make_uint2(h0, h1);
            *(uint2*)(csm + CX_AL + row * TS + c4 * 8) = make_uint2(l0, l1);
        }
        // B: 128x64 bf16 hi/lo from presplit qw (4 uint4 per thread each)
        #pragma unroll
        for (int i = 0; i < 4; i++) {
            int t = tid + i * 256;                 // 0..1023
            int row = t >> 3, g = t & 7;
            size_t src = (size_t)row * DM + ch * 64 + g * 8;
            uint32_t dst = (uint32_t)row * TS + g * 16;
            *(uint4*)(csm + CX_BH + dst) = *(const uint4*)(g_qw_hi + src);
            *(uint4*)(csm + CX_BL + dst) = *(const uint4*)(g_qw_lo + src);
        }
        __syncthreads();

        #pragma unroll
        for (int ks = 0; ks < 4; ks++) {
            uint32_t ah[2][4], al[2][4];
            uint32_t abase = (uint32_t)(wm * 32 + gid) * TS + tig * 4 + ks * 32;
            #pragma unroll
            for (int mt = 0; mt < 2; mt++) {
                uint32_t o = abase + mt * (16 * TS);
                ah[mt][0] = *(const uint32_t*)(csm + CX_AH + o);
                ah[mt][1] = *(const uint32_t*)(csm + CX_AH + o + 8 * TS);
                ah[mt][2] = *(const uint32_t*)(csm + CX_AH + o + 16);
                ah[mt][3] = *(const uint32_t*)(csm + CX_AH + o + 8 * TS + 16);
                al[mt][0] = *(const uint32_t*)(csm + CX_AL + o);
                al[mt][1] = *(const uint32_t*)(csm + CX_AL + o + 8 * TS);
                al[mt][2] = *(const uint32_t*)(csm + CX_AL + o + 16);
                al[mt][3] = *(const uint32_t*)(csm + CX_AL + o + 8 * TS + 16);
            }
            // pass-outer order: consecutive MMAs hit different accumulators
            #pragma unroll
            for (int pass = 0; pass < 3; pass++) {
                const char* bbuf = csm + ((pass == 1) ? CX_BL : CX_BH);
                #pragma unroll
                for (int nt = 0; nt < 4; nt++) {
                    uint32_t bbase = (uint32_t)(wn * 32 + nt * 8 + gid) * TS + tig * 4 + ks * 32;
                    uint32_t b0 = *(const uint32_t*)(bbuf + bbase);
                    uint32_t b1 = *(const uint32_t*)(bbuf + bbase + 16);
                    #pragma unroll
                    for (int mt = 0; mt < 2; mt++)
                        MMA16816(acc[mt][nt], (pass == 2) ? al[mt] : ah[mt], b0, b1);
                }
            }
        }
    }
    // epilogue: bias, pad, write fp32 + hi/lo split
    #pragma unroll
    for (int mt = 0; mt < 2; mt++)
        #pragma unroll
        for (int rh = 0; rh < 2; rh++) {
            int row = m0 + wm * 32 + mt * 16 + rh * 8 + gid;
            #pragma unroll
            for (int nt = 0; nt < 4; nt++)
                #pragma unroll
                for (int e = 0; e < 2; e++) {
                    int col = wn * 32 + nt * 8 + tig * 2 + e;
                    float v = (col < HD) ? (acc[mt][nt][rh * 2 + e] + qb[col]) : 0.0f;
                    size_t idx = (size_t)row * HP + col;
                    g_ctx[idx] = v;
                    __nv_bfloat16 vh = __float2bfloat16(v);
                    g_ctx_hi[idx] = vh;
                    g_ctx_lo[idx] = __float2bfloat16(v - __bfloat162float(vh));
                }
        }
}

// ---------------------------------------------------------
// trans = ctx @ DW (K=128) -> bf16 hi/lo; norm = sum(trans*ctx)   (FFMA2)
// ---------------------------------------------------------
__global__ __launch_bounds__(256) void k_trans() {
    __shared__ float2 sA[8][65];
    __shared__ float2 sB[8][129];
    const int m0 = blockIdx.x * 64;
    const int tid = threadIdx.x;
    const int tx = tid & 15, ty = tid >> 4;
    ull acc[4][8] = {};

    for (int kc = 0; kc < HP; kc += 16) {
        {
            int m  = tid >> 2;
            int k4 = (tid & 3) * 4;
            int kk = (tid & 3) * 2;
            float4 v = *(const float4*)(g_ctx + (size_t)(m0 + m) * HP + kc + k4);
            sA[kk][m]     = make_float2(v.x, v.y);
            sA[kk + 1][m] = make_float2(v.z, v.w);
        }
        #pragma unroll
        for (int r2 = 0; r2 < 2; r2++) {
            int t4 = tid + 256 * r2;
            int n  = t4 >> 2;
            int k4 = (t4 & 3) * 4;
            int kk = (t4 & 3) * 2;
            float4 v = *(const float4*)(g_dw + (size_t)n * HP + kc + k4);
            sB[kk][n]     = make_float2(v.x, v.y);
            sB[kk + 1][n] = make_float2(v.z, v.w);
        }
        __syncthreads();
        #pragma unroll
        for (int kk = 0; kk < 8; kk++) {
            ull a2[4], b2[8];
            #pragma unroll
            for (int r = 0; r < 4; r++) a2[r] = *(const ull*)&sA[kk][ty + r * 16];
            #pragma unroll
            for (int c = 0; c < 8; c++) b2[c] = *(const ull*)&sB[kk][tx + c * 16];
            #pragma unroll
            for (int r = 0; r < 4; r++)
                #pragma unroll
                for (int c = 0; c < 8; c++)
                    FMA2(acc[r][c], a2[r], b2[c]);
        }
        __syncthreads();
    }
    float pn[4] = {};
    #pragma unroll
    for (int r = 0; r < 4; r++) {
        int m = m0 + ty + r * 16;
        #pragma unroll
        for (int c = 0; c < 8; c++) {
            int n = tx + c * 16;
            float lo, hi; UNPACK2(lo, hi, acc[r][c]);
            float v = lo + hi;                       // exact 0 for n>=120
            size_t idx = (size_t)m * HP + n;
            __nv_bfloat16 vh = __float2bfloat16(v);
            g_tr_hi[idx] = vh;
            g_tr_lo[idx] = __float2bfloat16(v - __bfloat162float(vh));
            pn[r] = fmaf(v, g_ctx[idx], pn[r]);
        }
    }
    #pragma unroll
    for (int r = 0; r < 4; r++) {
        float s = pn[r];
        #pragma unroll
        for (int m2 = 8; m2 >= 1; m2 >>= 1)
            s += __shfl_xor_sync(0xffffffffu, s, m2);
        if (tx == 0) g_norm[m0 + ty + r * 16] = s;
    }
}

// ---------------------------------------------------------
// Tensor-core scores (HMMA split-bf16, pass-outer MMA order),
// fused double-exp + rowsum + smem-staged coalesced stores.
// grid (16,16,8), 256 threads; warp grid 4(m) x 2(n), warp tile 32x64.
// ---------------------------------------------------------
#define TILE_B   (128 * TS)           // 18432 B per tile
#define SC_SROW  16                   // 128 f32 rowsum partials
#define SC_SNI   544                  // 128 f32 norm_i
#define SC_SNJ   1072                 // 128 f32 norm_j
#define SC_AH    2048
#define SC_AL    (SC_AH + TILE_B)
#define SC_BH    (SC_AL + TILE_B)
#define SC_BL    (SC_BH + TILE_B)
#define SC_SMEM_TOTAL (SC_BL + TILE_B)        // 75776
#define SC_OUT   2048                 // epilogue staging reuses tile region
#define OUT_P    130                  // staging pitch (floats): even -> aligned float2

__global__ __launch_bounds__(256) void k_scores_mma(const float* __restrict__ pinv,
                                                    float* __restrict__ out) {
    extern __shared__ char smem[];
    const int tid  = threadIdx.x;
    const int wid  = tid >> 5, lane = tid & 31;
    const int gid  = lane >> 2, tig = lane & 3;
    const int wm   = wid & 3;          // warp row (0..3) -> rows 32*wm
    const int wn   = wid >> 2;         // warp col (0..1) -> cols 64*wn
    const int b  = blockIdx.z;
    const int i0 = blockIdx.y * 128;
    const int j0 = blockIdx.x * 128;

    const __nv_bfloat16* Ah = g_tr_hi  + (size_t)b * LL * HP;
    const __nv_bfloat16* Al = g_tr_lo  + (size_t)b * LL * HP;
    const __nv_bfloat16* Bh = g_ctx_hi + (size_t)b * LL * HP;
    const __nv_bfloat16* Bl = g_ctx_lo + (size_t)b * LL * HP;

    if (tid < 128) {
        *(float*)(smem + SC_SROW + tid * 4) = 0.0f;
        *(float*)(smem + SC_SNI  + tid * 4) = g_norm[(size_t)b * LL + i0 + tid];
        *(float*)(smem + SC_SNJ  + tid * 4) = g_norm[(size_t)b * LL + j0 + tid];
    }

    float acc[2][8][4] = {};       // [mt][nt][c]

    #pragma unroll 1
    for (int ch = 0; ch < 2; ch++) {
        __syncthreads();
        #pragma unroll
        for (int it = 0; it < 4; it++) {
            int t = tid + it * 256;               // 0..1023
            int row = t >> 3, g = t & 7;
            uint32_t dst = (uint32_t)row * TS + g * 16;
            size_t sa  = (size_t)(i0 + row) * HP + ch * 64 + g * 8;
            size_t sb2 = (size_t)(j0 + row) * HP + ch * 64 + g * 8;
            *(uint4*)(smem + SC_AH + dst) = *(const uint4*)(Ah + sa);
            *(uint4*)(smem + SC_AL + dst) = *(const uint4*)(Al + sa);
            *(uint4*)(smem + SC_BH + dst) = *(const uint4*)(Bh + sb2);
            *(uint4*)(smem + SC_BL + dst) = *(const uint4*)(Bl + sb2);
        }
        __syncthreads();

        #pragma unroll
        for (int ks = 0; ks < 4; ks++) {
            uint32_t ah[2][4], al[2][4];
            uint32_t abase = (uint32_t)(wm * 32 + gid) * TS + tig * 4 + ks * 32;
            #pragma unroll
            for (int mt = 0; mt < 2; mt++) {
                uint32_t o = abase + mt * (16 * TS);
                ah[mt][0] = *(const uint32_t*)(smem + SC_AH + o);
                ah[mt][1] = *(const uint32_t*)(smem + SC_AH + o + 8 * TS);
                ah[mt][2] = *(const uint32_t*)(smem + SC_AH + o + 16);
                ah[mt][3] = *(const uint32_t*)(smem + SC_AH + o + 8 * TS + 16);
                al[mt][0] = *(const uint32_t*)(smem + SC_AL + o);
                al[mt][1] = *(const uint32_t*)(smem + SC_AL + o + 8 * TS);
                al[mt][2] = *(const uint32_t*)(smem + SC_AL + o + 16);
                al[mt][3] = *(const uint32_t*)(smem + SC_AL + o + 8 * TS + 16);
            }
            // pass-outer: consecutive MMAs use different accumulators (RAW dist 16)
            #pragma unroll
            for (int pass = 0; pass < 3; pass++) {
                const char* bbuf = smem + ((pass == 1) ? SC_BL : SC_BH);
                #pragma unroll
                for (int nt = 0; nt < 8; nt++) {
                    uint32_t bbase = (uint32_t)(wn * 64 + nt * 8 + gid) * TS + tig * 4 + ks * 32;
                    uint32_t b0 = *(const uint32_t*)(bbuf + bbase);
                    uint32_t b1 = *(const uint32_t*)(bbuf + bbase + 16);
                    #pragma unroll
                    for (int mt = 0; mt < 2; mt++)
                        MMA16816(acc[mt][nt], (pass == 2) ? al[mt] : ah[mt], b0, b1);
                }
            }
        }
    }
    __syncthreads();   // mma done -> staging region reusable

    const float pv = pinv[0];
    const float sc = 0.5f * pv * pv;

    #pragma unroll
    for (int mt = 0; mt < 2; mt++) {
        #pragma unroll
        for (int rh = 0; rh < 2; rh++) {
            int row = wm * 32 + mt * 16 + rh * 8 + gid;
            float ni = *(const float*)(smem + SC_SNI + row * 4);
            float rs = 0.0f;
            #pragma unroll
            for (int nt = 0; nt < 8; nt++) {
                int col = wn * 64 + nt * 8 + tig * 2;
                float nj0 = *(const float*)(smem + SC_SNJ + col * 4);
                float nj1 = *(const float*)(smem + SC_SNJ + col * 4 + 4);
                float g0 = acc[mt][nt][rh * 2 + 0];
                float g1 = acc[mt][nt][rh * 2 + 1];
                float e0 = __expf(__expf(-sc * (ni + nj0 - 2.0f * g0)));
                float e1 = __expf(__expf(-sc * (ni + nj1 - 2.0f * g1)));
                rs += e0 + e1;
                *(float2*)(smem + SC_OUT + (row * OUT_P + col) * 4) = make_float2(e0, e1);
            }
            rs += __shfl_xor_sync(0xffffffffu, rs, 1);
            rs += __shfl_xor_sync(0xffffffffu, rs, 2);
            if (tig == 0)
                atomicAdd((float*)(smem + SC_SROW + row * 4), rs);
        }
    }
    __syncthreads();
    if (tid < 128)
        atomicAdd(&g_rowsum[(size_t)b * LL + i0 + tid],
                  *(const float*)(smem + SC_SROW + tid * 4));

    // fully-coalesced store of the 128x128 tile
    #pragma unroll 8
    for (int it = 0; it < 64; it++) {
        int lin = it * 256 + tid;
        int row = lin >> 7, col = lin & 127;
        out[((size_t)b * LL + i0 + row) * LL + j0 + col] =
            *(const float*)(smem + SC_OUT + (row * OUT_P + col) * 4);
    }
}

// ---------------------------------------------------------
// out /= rowsum (streaming, float4)
// ---------------------------------------------------------
__global__ void k_norm(float* __restrict__ out) {
    size_t idx = (size_t)blockIdx.x * blockDim.x + threadIdx.x;
    const size_t total4 = (size_t)M_TOTAL * LL / 4;
    if (idx < total4) {
        size_t row = idx >> 9;
        float r = 1.0f / g_rowsum[row];
        float4 v = ((const float4*)out)[idx];
        v.x *= r; v.y *= r; v.z *= r; v.w *= r;
        ((float4*)out)[idx] = v;
    }
}

// ---------------------------------------------------------
extern "C" void kernel_launch(void* const* d_in, const int* in_sizes, int n_in,
                              void* d_out, int out_size) {
    const float* Q    = (const float*)d_in[0];
    const float* qw   = (const float*)d_in[2];
    const float* qb   = (const float*)d_in[3];
    const float* W    = (const float*)d_in[4];
    const float* pinv = (const float*)d_in[5];
    float* out = (float*)d_out;

    // idempotent, capture-legal; called every time (no static guards allowed)
    cudaFuncSetAttribute(k_scores_mma, cudaFuncAttributeMaxDynamicSharedMemorySize,
                         SC_SMEM_TOTAL);
    cudaFuncSetAttribute(k_ctx_mma, cudaFuncAttributeMaxDynamicSharedMemorySize,
                         CX_SMEM);

    k_zero<<<(M_TOTAL + 255) / 256, 256>>>();
    k_wsplit<<<(HP * DM) / 256, 256>>>(qw);
    k_dw<<<128, 128>>>(W);
    k_ctx_mma<<<M_TOTAL / 64, 256, CX_SMEM>>>(Q, qb);
    k_trans<<<M_TOTAL / 64, 256>>>();
    dim3 gs(LL / 128, LL / 128, BB);
    k_scores_mma<<<gs, 256, SC_SMEM_TOTAL>>>(pinv, out);
    size_t total4 = (size_t)M_TOTAL * LL / 4;
    k_norm<<<(unsigned)((total4 + 255) / 256), 256>>>(out);
}